// round 4
// baseline (speedup 1.0000x reference)
#include <cuda_runtime.h>

// Problem dims (fixed by dataset)
#define BB 4
#define NN 4096
#define CC 256
#define MM 2048

#define TAU_F 0.4f
#define EPS_F 1e-8f

// Tiling
#define TN  32      // l-rows per block
#define TMC 128     // M chunk
#define LSTR 260    // Ls row stride (floats), multiple of 4 for float4
#define GSTR 129    // Gs row stride (odd -> conflict-free both phases)
#define WSTR 33     // Wt row stride (odd)

__device__ float d_lnorm[BB * NN];
__device__ float d_gnorm[BB * MM];

// ---------------------------------------------------------------------------
// Norm precompute
// ---------------------------------------------------------------------------
__global__ void lnorm_kernel(const float* __restrict__ l) {
    int row  = blockIdx.x * 8 + (threadIdx.x >> 5);   // one warp per row
    int lane = threadIdx.x & 31;
    const float* p = l + (size_t)row * CC;
    float s = 0.f;
#pragma unroll
    for (int c = lane; c < CC; c += 32) { float v = p[c]; s = fmaf(v, v, s); }
#pragma unroll
    for (int o = 16; o; o >>= 1) s += __shfl_xor_sync(0xffffffffu, s, o);
    if (lane == 0) d_lnorm[row] = sqrtf(s);
}

__global__ void gnorm_kernel(const float* __restrict__ g) {
    int idx = blockIdx.x * blockDim.x + threadIdx.x;  // 0..BB*MM-1
    int b = idx / MM, m = idx % MM;
    const float* p = g + (size_t)b * CC * MM + m;
    float s = 0.f;
#pragma unroll 8
    for (int c = 0; c < CC; c++) { float v = p[(size_t)c * MM]; s = fmaf(v, v, s); }
    d_gnorm[idx] = sqrtf(s);
}

// ---------------------------------------------------------------------------
// Fused: S = L*G (cos-scaled, exp), rowsum, O += W*G^T, out = L + O/rowsum
// ---------------------------------------------------------------------------
__global__ __launch_bounds__(256, 1)
void fused_kernel(const float* __restrict__ l, const float* __restrict__ g,
                  float* __restrict__ out) {
    extern __shared__ float sm[];
    float* Gs = sm;                     // [CC][GSTR]
    float* Ls = Gs + CC * GSTR;         // [TN][LSTR]
    float* Wt = Ls + TN * LSTR;         // [TMC][WSTR]  Wt[j][i]

    const int b  = blockIdx.y;
    const int n0 = blockIdx.x * TN;
    const int t  = threadIdx.x;
    const int tx = t & 31;              // lane
    const int ty = t >> 5;              // warp id (0..7)

    const float* lb = l + ((size_t)b * NN + n0) * CC;
    const float* gb = g + (size_t)b * CC * MM;

    // Stage L tile (vectorized; lanes write consecutive floats -> no conflicts)
    for (int f = t; f < TN * CC / 4; f += 256) {
        int n  = f >> 6;                // 64 float4 per row
        int c4 = f & 63;
        float4 v = ((const float4*)lb)[f];
        *((float4*)(Ls + n * LSTR) + c4) = v;
    }

    float ln[4];
#pragma unroll
    for (int ii = 0; ii < 4; ii++) ln[ii] = d_lnorm[b * NN + n0 + ty + 8 * ii];

    float O[4][8];
#pragma unroll
    for (int ii = 0; ii < 4; ii++)
#pragma unroll
        for (int cc = 0; cc < 8; cc++) O[ii][cc] = 0.f;
    float rs[4] = {0.f, 0.f, 0.f, 0.f};

    for (int m0 = 0; m0 < MM; m0 += TMC) {
        // ---- Stage G chunk: Gs[c][m], m local ----
        for (int f = t; f < CC * TMC / 4; f += 256) {
            int c  = f >> 5;            // 32 float4 per row
            int m4 = (f & 31) << 2;
            float4 v = *((const float4*)(gb + (size_t)c * MM + m0 + m4));
            float* dst = Gs + c * GSTR + m4;
            dst[0] = v.x; dst[1] = v.y; dst[2] = v.z; dst[3] = v.w;
        }
        __syncthreads();

        float gn[4];
#pragma unroll
        for (int jj = 0; jj < 4; jj++) gn[jj] = d_gnorm[b * MM + m0 + tx + 32 * jj];

        // ---- Phase A: S[4][4] = L_tile . G_chunk ----
        float S[4][4];
#pragma unroll
        for (int ii = 0; ii < 4; ii++)
#pragma unroll
            for (int jj = 0; jj < 4; jj++) S[ii][jj] = 0.f;

#pragma unroll 2
        for (int c = 0; c < CC; c += 4) {
            float4 lv[4];
#pragma unroll
            for (int ii = 0; ii < 4; ii++)
                lv[ii] = *(const float4*)(Ls + (ty + 8 * ii) * LSTR + c);
#pragma unroll
            for (int cs = 0; cs < 4; cs++) {
                float gv[4];
#pragma unroll
                for (int jj = 0; jj < 4; jj++)
                    gv[jj] = Gs[(c + cs) * GSTR + tx + 32 * jj];
#pragma unroll
                for (int ii = 0; ii < 4; ii++) {
                    const float* lp = (const float*)&lv[ii];
                    float la = lp[cs];
#pragma unroll
                    for (int jj = 0; jj < 4; jj++)
                        S[ii][jj] = fmaf(la, gv[jj], S[ii][jj]);
                }
            }
        }

        // ---- exp(cos/tau), rowsum, store W transposed ----
#pragma unroll
        for (int ii = 0; ii < 4; ii++) {
#pragma unroll
            for (int jj = 0; jj < 4; jj++) {
                float prod = fmaxf(ln[ii] * gn[jj], EPS_F);
                float w = __expf(__fdividef(S[ii][jj], prod * TAU_F));
                rs[ii] += w;
                Wt[(tx + 32 * jj) * WSTR + ty + 8 * ii] = w;
            }
        }
        __syncthreads();

        // ---- Phase B: O[i][c] += sum_j W[i][j] * G[c][j] ----
#pragma unroll 4
        for (int j = 0; j < TMC; j++) {
            float wv[4];
#pragma unroll
            for (int ii = 0; ii < 4; ii++) wv[ii] = Wt[j * WSTR + ty + 8 * ii];
            float gv[8];
#pragma unroll
            for (int cc = 0; cc < 8; cc++) gv[cc] = Gs[(tx + 32 * cc) * GSTR + j];
#pragma unroll
            for (int ii = 0; ii < 4; ii++)
#pragma unroll
                for (int cc = 0; cc < 8; cc++)
                    O[ii][cc] = fmaf(wv[ii], gv[cc], O[ii][cc]);
        }
        __syncthreads();   // before next chunk overwrites Gs/Wt
    }

    // ---- rowsum reduce (lanes of a warp share ty -> full row) ----
#pragma unroll
    for (int ii = 0; ii < 4; ii++) {
#pragma unroll
        for (int o = 16; o; o >>= 1)
            rs[ii] += __shfl_xor_sync(0xffffffffu, rs[ii], o);
    }

    // ---- Epilogue: out = l + O / rowsum ----
#pragma unroll
    for (int ii = 0; ii < 4; ii++) {
        float rinv = 1.0f / rs[ii];
        int n = ty + 8 * ii;
        float* op = out + ((size_t)b * NN + n0 + n) * CC;
#pragma unroll
        for (int cc = 0; cc < 8; cc++) {
            int c = tx + 32 * cc;
            op[c] = Ls[n * LSTR + c] + O[ii][cc] * rinv;
        }
    }
}

// ---------------------------------------------------------------------------
extern "C" void kernel_launch(void* const* d_in, const int* in_sizes, int n_in,
                              void* d_out, int out_size) {
    const float* l = (const float*)d_in[0];   // [B, N, C]
    const float* g = (const float*)d_in[1];   // [B, C, M]
    float* out = (float*)d_out;               // [B, N, C]

    const size_t smem = (size_t)(CC * GSTR + TN * LSTR + TMC * WSTR) * sizeof(float);
    cudaFuncSetAttribute(fused_kernel,
                         cudaFuncAttributeMaxDynamicSharedMemorySize, (int)smem);

    lnorm_kernel<<<BB * NN / 8, 256>>>(l);
    gnorm_kernel<<<BB * MM / 256, 256>>>(g);
    fused_kernel<<<dim3(NN / TN, BB), 256, smem>>>(l, g, out);
}

// round 11
// speedup vs baseline: 6.0900x; 6.0900x over previous
#include <cuda_runtime.h>
#include <cuda_bf16.h>
#include <stdint.h>

#define BB 4
#define NN 4096
#define CC 256
#define MM 2048
#define TAU_F 0.4f
#define LOG2E 1.4426950408889634f

#define TMC 64
#define NCH (MM / TMC)          // 32 chunks
#define TILE_N 128
#define NTILES (NN / TILE_N)    // 32 tiles
#define LPAD 264                // halves per L row (528 B = 33*16B -> conflict-free LDSM)

#define SM_LS 0
#define LS_BYTES (TILE_N * LPAD * 2)      // 67584 = 4224 uint4
#define LS_U4 (LS_BYTES / 16)             // 4224
#define SM_GS LS_BYTES                    // 67584 (1024-aligned)
#define GS_BYTES (CC * TMC * 2)           // 32768
#define SM_GN (SM_GS + 2 * GS_BYTES)      // 133120
#define SMEM_ALLOC (SM_GN + 512 + 1024)

__device__ __align__(16) __nv_bfloat16 d_Lbf[BB * NTILES * TILE_N * LPAD];
__device__ __align__(16) __nv_bfloat16 d_Gbf[BB * NCH * CC * TMC];
__device__ float d_rln[BB * NN];   // log2e / (tau * ||l_n||)
__device__ float d_rgn[BB * MM];   // 1 / ||g_m||

// ---------------------------------------------------------------------------
__device__ __forceinline__ uint32_t smem_u32(const void* p) {
    uint32_t a;
    asm("{ .reg .u64 t; cvta.to.shared.u64 t, %1; cvt.u32.u64 %0, t; }" : "=r"(a) : "l"(p));
    return a;
}

__device__ __forceinline__ void ldsm_x4(uint32_t a, uint32_t* r) {
    asm volatile("ldmatrix.sync.aligned.m8n8.x4.shared.b16 {%0,%1,%2,%3}, [%4];"
                 : "=r"(r[0]), "=r"(r[1]), "=r"(r[2]), "=r"(r[3]) : "r"(a));
}
__device__ __forceinline__ void ldsm_x4t(uint32_t a, uint32_t* r) {
    asm volatile("ldmatrix.sync.aligned.m8n8.x4.trans.shared.b16 {%0,%1,%2,%3}, [%4];"
                 : "=r"(r[0]), "=r"(r[1]), "=r"(r[2]), "=r"(r[3]) : "r"(a));
}
__device__ __forceinline__ void mma16816(float* d, const uint32_t* a, uint32_t b0, uint32_t b1) {
    asm volatile("mma.sync.aligned.m16n8k16.row.col.f32.bf16.bf16.f32 "
                 "{%0,%1,%2,%3}, {%4,%5,%6,%7}, {%8,%9}, {%0,%1,%2,%3};"
                 : "+f"(d[0]), "+f"(d[1]), "+f"(d[2]), "+f"(d[3])
                 : "r"(a[0]), "r"(a[1]), "r"(a[2]), "r"(a[3]), "r"(b0), "r"(b1));
}
__device__ __forceinline__ float ex2f(float x) {
    float r; asm("ex2.approx.ftz.f32 %0, %1;" : "=f"(r) : "f"(x)); return r;
}

// ---------------------------------------------------------------------------
// prep_l: row-major bf16 tile, row stride LPAD halves; plus rln
// ---------------------------------------------------------------------------
__global__ __launch_bounds__(128) void prep_l_kernel(const float* __restrict__ l) {
    const int bt = blockIdx.x;                 // b*NTILES + tile
    const int i = threadIdx.x;                 // row in tile
    const int rowg = bt * TILE_N + i;
    const float4* src = (const float4*)(l + (size_t)rowg * CC);
    __nv_bfloat162* dst = (__nv_bfloat162*)(d_Lbf + (size_t)bt * TILE_N * LPAD + (size_t)i * LPAD);
    float s = 0.f;
#pragma unroll
    for (int qq = 0; qq < 64; qq++) {
        float4 v = src[qq];
        s = fmaf(v.x, v.x, fmaf(v.y, v.y, fmaf(v.z, v.z, fmaf(v.w, v.w, s))));
        dst[2 * qq]     = __floats2bfloat162_rn(v.x, v.y);
        dst[2 * qq + 1] = __floats2bfloat162_rn(v.z, v.w);
    }
    d_rln[rowg] = LOG2E / (TAU_F * sqrtf(s));
}

// ---------------------------------------------------------------------------
// prep_g: bf16 chunk [c][64m], 128B rows, swizzled; plus rgn
// ---------------------------------------------------------------------------
__global__ __launch_bounds__(128) void prep_g_kernel(const float* __restrict__ g) {
    const int idx = blockIdx.x * 128 + threadIdx.x;   // 0..BB*MM/2-1
    const int b = idx / (MM / 2);
    const int m0 = (idx % (MM / 2)) * 2;
    const int chunk = m0 / TMC;
    const int j = m0 % TMC;
    const float* gp = g + (size_t)b * CC * MM + m0;
    char* dstb = (char*)(d_Gbf + (size_t)(b * NCH + chunk) * CC * TMC);
    float s0 = 0.f, s1 = 0.f;
#pragma unroll 8
    for (int c = 0; c < CC; c++) {
        float2 v = *(const float2*)(gp + (size_t)c * MM);
        s0 = fmaf(v.x, v.x, s0);
        s1 = fmaf(v.y, v.y, s1);
        uint32_t off = (uint32_t)(c * 128 + j * 2);
        off ^= (uint32_t)((c & 7) << 4);               // swizzle bits 4-6 by c&7
        *(__nv_bfloat162*)(dstb + off) = __floats2bfloat162_rn(v.x, v.y);
    }
    d_rgn[b * MM + m0]     = rsqrtf(s0);
    d_rgn[b * MM + m0 + 1] = rsqrtf(s1);
}

// ---------------------------------------------------------------------------
// Fused: GEMM1 (S = L.G) -> exp -> GEMM2 (O += W.G^T) -> out = l + O/rowsum
// ---------------------------------------------------------------------------
__global__ __launch_bounds__(256, 1)
void fused_mma_kernel(const float* __restrict__ l, float* __restrict__ out) {
    extern __shared__ char smraw[];
    char* gb = (char*)(((uintptr_t)smraw + 1023) & ~(uintptr_t)1023);
    const uint32_t base = smem_u32(gb);
    const int t = threadIdx.x, lane = t & 31, wid = t >> 5;
    const int q = lane & 3, lr = lane & 7, lg = lane >> 3;
    const int b = blockIdx.y, tile = blockIdx.x;

    // Stage L tile (flat copy; tile is exactly LS_U4 uint4)
    {
        const uint4* s4 = (const uint4*)(d_Lbf + (size_t)(b * NTILES + tile) * TILE_N * LPAD);
        uint4* d4 = (uint4*)(gb + SM_LS);
        for (int i = t; i < LS_U4; i += 256) d4[i] = s4[i];
    }
    // Stage G chunk 0 + gn chunk 0
    {
        const uint4* s4 = (const uint4*)(d_Gbf + (size_t)(b * NCH) * CC * TMC);
        uint4* d4 = (uint4*)(gb + SM_GS);
#pragma unroll
        for (int i = 0; i < 8; i++) d4[t + 256 * i] = s4[t + 256 * i];
        if (t < 16) ((uint4*)(gb + SM_GN))[t] = ((const uint4*)(d_rgn + b * MM))[t];
    }

    const int row0 = tile * TILE_N + wid * 16 + (lane >> 2);  // lower row of this thread
    const float rln_lo = d_rln[b * NN + row0];
    const float rln_hi = d_rln[b * NN + row0 + 8];

    // ldmatrix addresses (16B-granular)
    const uint32_t aA0 = base + SM_LS
        + (uint32_t)((wid * 16 + (lg & 1) * 8 + lr) * (LPAD * 2)) + (uint32_t)((lg >> 1) * 16);
    uint32_t b1off[4];   // GEMM1 B (trans): c = kt*16 + (lg&1)*8 + lr; pair pp covers ntiles 2pp,2pp+1
#pragma unroll
    for (int pp = 0; pp < 4; pp++)
        b1off[pp] = (uint32_t)(((lg & 1) * 8 + lr) * 128)
                  + ((uint32_t)(pp * 32 + (lg >> 1) * 16) ^ (uint32_t)(lr << 4));
    const uint32_t b2off0 = (uint32_t)(lr * 128) + ((uint32_t)(lg * 16) ^ (uint32_t)(lr << 4));
    const uint32_t b2off1 = (uint32_t)(lr * 128) + ((uint32_t)(64 + lg * 16) ^ (uint32_t)(lr << 4));

    float O[32][4];
#pragma unroll
    for (int nt = 0; nt < 32; nt++) { O[nt][0] = O[nt][1] = O[nt][2] = O[nt][3] = 0.f; }
    float rs_lo = 0.f, rs_hi = 0.f;

    __syncthreads();

    for (int k = 0; k < NCH; k++) {
        const int s = k & 1;
        const uint32_t Gsb = base + SM_GS + (uint32_t)(s * GS_BYTES);

        // Prefetch next chunk into the other slot (read in iter k+1, after the barrier)
        if (k + 1 < NCH) {
            const uint4* s4 = (const uint4*)(d_Gbf + (size_t)(b * NCH + k + 1) * CC * TMC);
            uint4* d4 = (uint4*)(gb + SM_GS + (s ^ 1) * GS_BYTES);
#pragma unroll
            for (int i = 0; i < 8; i++) d4[t + 256 * i] = s4[t + 256 * i];
            if (t < 16)
                ((uint4*)(gb + SM_GN + (s ^ 1) * 256))[t] =
                    ((const uint4*)(d_rgn + b * MM + (k + 1) * TMC))[t];
        }

        // ---- GEMM1: S[16 rows][64 cols] per warp ----
        float S[8][4];
#pragma unroll
        for (int p = 0; p < 8; p++) S[p][0] = S[p][1] = S[p][2] = S[p][3] = 0.f;
#pragma unroll
        for (int kt = 0; kt < 16; kt++) {
            uint32_t A[4];
            ldsm_x4(aA0 + (uint32_t)(kt * 32), A);
            const uint32_t crow = Gsb + (uint32_t)(kt * 2048);
#pragma unroll
            for (int pp = 0; pp < 4; pp++) {
                uint32_t B4[4];
                ldsm_x4t(crow + b1off[pp], B4);
                mma16816(S[2 * pp],     A, B4[0], B4[1]);
                mma16816(S[2 * pp + 1], A, B4[2], B4[3]);
            }
        }

        // ---- exp -> W fragments (registers only) + rowsum ----
        const float* gnp = (const float*)(gb + SM_GN + s * 256);
        uint32_t afr[4][4];
#pragma unroll
        for (int p = 0; p < 8; p++) {
            float2 gn2 = *(const float2*)(gnp + p * 8 + q * 2);
            float w0 = ex2f(S[p][0] * rln_lo * gn2.x);
            float w1 = ex2f(S[p][1] * rln_lo * gn2.y);
            float w2 = ex2f(S[p][2] * rln_hi * gn2.x);
            float w3 = ex2f(S[p][3] * rln_hi * gn2.y);
            rs_lo += w0 + w1;
            rs_hi += w2 + w3;
            uint32_t pk01, pk23;
            asm("cvt.rn.bf16x2.f32 %0, %1, %2;" : "=r"(pk01) : "f"(w1), "f"(w0));
            asm("cvt.rn.bf16x2.f32 %0, %1, %2;" : "=r"(pk23) : "f"(w3), "f"(w2));
            afr[p >> 1][(p & 1) * 2 + 0] = pk01;
            afr[p >> 1][(p & 1) * 2 + 1] = pk23;
        }

        // ---- GEMM2: O[16 rows][256 cols] += W[16][64] . G^T[64][256] ----
#pragma unroll
        for (int nt = 0; nt < 32; nt++) {
            const uint32_t nb = Gsb + (uint32_t)(nt * 1024);
            uint32_t B0[4], B1[4];
            ldsm_x4(nb + b2off0, B0);
            ldsm_x4(nb + b2off1, B1);
            mma16816(O[nt], afr[0], B0[0], B0[1]);
            mma16816(O[nt], afr[1], B0[2], B0[3]);
            mma16816(O[nt], afr[2], B1[0], B1[1]);
            mma16816(O[nt], afr[3], B1[2], B1[3]);
        }
        __syncthreads();
    }

    // ---- rowsum reduce across the lane quad (cols partition over q) ----
    rs_lo += __shfl_xor_sync(0xffffffffu, rs_lo, 1);
    rs_lo += __shfl_xor_sync(0xffffffffu, rs_lo, 2);
    rs_hi += __shfl_xor_sync(0xffffffffu, rs_hi, 1);
    rs_hi += __shfl_xor_sync(0xffffffffu, rs_hi, 2);
    const float ri_lo = 1.0f / rs_lo;
    const float ri_hi = 1.0f / rs_hi;

    // ---- Epilogue: out = l + O / rowsum ----
    const float* lrow_lo = l + ((size_t)b * NN + row0) * CC;
    const float* lrow_hi = lrow_lo + 8 * CC;
    float* orow_lo = out + ((size_t)b * NN + row0) * CC;
    float* orow_hi = orow_lo + 8 * CC;
#pragma unroll
    for (int nt = 0; nt < 32; nt++) {
        const int c = nt * 8 + q * 2;
        float2 lv0 = *(const float2*)(lrow_lo + c);
        float2 ov0;
        ov0.x = fmaf(O[nt][0], ri_lo, lv0.x);
        ov0.y = fmaf(O[nt][1], ri_lo, lv0.y);
        *(float2*)(orow_lo + c) = ov0;
        float2 lv1 = *(const float2*)(lrow_hi + c);
        float2 ov1;
        ov1.x = fmaf(O[nt][2], ri_hi, lv1.x);
        ov1.y = fmaf(O[nt][3], ri_hi, lv1.y);
        *(float2*)(orow_hi + c) = ov1;
    }
}

// ---------------------------------------------------------------------------
extern "C" void kernel_launch(void* const* d_in, const int* in_sizes, int n_in,
                              void* d_out, int out_size) {
    (void)in_sizes; (void)n_in; (void)out_size;
    const float* l = (const float*)d_in[0];   // [B, N, C]
    const float* g = (const float*)d_in[1];   // [B, C, M]
    float* out = (float*)d_out;               // [B, N, C]

    cudaFuncSetAttribute(fused_mma_kernel,
                         cudaFuncAttributeMaxDynamicSharedMemorySize, SMEM_ALLOC);

    prep_l_kernel<<<BB * NTILES, 128>>>(l);
    prep_g_kernel<<<BB * MM / 2 / 128, 128>>>(g);
    fused_mma_kernel<<<dim3(NTILES, BB), 256, SMEM_ALLOC>>>(l, out);
}

// round 12
// speedup vs baseline: 9.5653x; 1.5707x over previous
#include <cuda_runtime.h>
#include <cuda_bf16.h>
#include <stdint.h>

#define BB 4
#define NN 4096
#define CC 256
#define MM 2048
#define TAU_F 0.4f
#define LOG2E 1.4426950408889634f

#define TMC 64
#define NCH (MM / TMC)          // 32 chunks
#define TILE_N 128
#define NTILES (NN / TILE_N)    // 32 tiles
#define LPAD 264                // halves per L row (528 B = 33*16B -> conflict-free LDSM)

#define SM_LS 0
#define LS_BYTES (TILE_N * LPAD * 2)      // 67584 = 4224 uint4
#define LS_U4 (LS_BYTES / 16)             // 4224
#define SM_GS LS_BYTES                    // 67584 (1024-aligned)
#define GS_BYTES (CC * TMC * 2)           // 32768
#define SM_GN (SM_GS + 2 * GS_BYTES)      // 133120
#define SMEM_ALLOC (SM_GN + 512 + 1024)

#define NLBLK (BB * NN / 8)               // 2048 L-blocks (8 rows each)

__device__ __align__(16) __nv_bfloat16 d_Lbf[BB * NTILES * TILE_N * LPAD];
__device__ __align__(16) __nv_bfloat16 d_Gbf[BB * NCH * CC * TMC];
__device__ float d_rln[BB * NN];   // log2e / (tau * ||l_n||)
__device__ float d_rgn[BB * MM];   // 1 / ||g_m||

// ---------------------------------------------------------------------------
__device__ __forceinline__ uint32_t smem_u32(const void* p) {
    uint32_t a;
    asm("{ .reg .u64 t; cvta.to.shared.u64 t, %1; cvt.u32.u64 %0, t; }" : "=r"(a) : "l"(p));
    return a;
}
__device__ __forceinline__ void ldsm_x4(uint32_t a, uint32_t* r) {
    asm volatile("ldmatrix.sync.aligned.m8n8.x4.shared.b16 {%0,%1,%2,%3}, [%4];"
                 : "=r"(r[0]), "=r"(r[1]), "=r"(r[2]), "=r"(r[3]) : "r"(a));
}
__device__ __forceinline__ void ldsm_x4t(uint32_t a, uint32_t* r) {
    asm volatile("ldmatrix.sync.aligned.m8n8.x4.trans.shared.b16 {%0,%1,%2,%3}, [%4];"
                 : "=r"(r[0]), "=r"(r[1]), "=r"(r[2]), "=r"(r[3]) : "r"(a));
}
__device__ __forceinline__ void mma16816(float* d, const uint32_t* a, uint32_t b0, uint32_t b1) {
    asm volatile("mma.sync.aligned.m16n8k16.row.col.f32.bf16.bf16.f32 "
                 "{%0,%1,%2,%3}, {%4,%5,%6,%7}, {%8,%9}, {%0,%1,%2,%3};"
                 : "+f"(d[0]), "+f"(d[1]), "+f"(d[2]), "+f"(d[3])
                 : "r"(a[0]), "r"(a[1]), "r"(a[2]), "r"(a[3]), "r"(b0), "r"(b1));
}
__device__ __forceinline__ float ex2f(float x) {
    float r; asm("ex2.approx.ftz.f32 %0, %1;" : "=f"(r) : "f"(x)); return r;
}
__device__ __forceinline__ void cpasync16(uint32_t dst, const void* src) {
    asm volatile("cp.async.cg.shared.global [%0], [%1], 16;" :: "r"(dst), "l"(src) : "memory");
}

// ---------------------------------------------------------------------------
// Merged prep: blocks [0,NLBLK) do L (warp per row); blocks [NLBLK, +128) do G
// ---------------------------------------------------------------------------
__global__ __launch_bounds__(256) void prep_kernel(const float* __restrict__ l,
                                                   const float* __restrict__ g) {
    __shared__ float2 part[8][32];
    if (blockIdx.x < NLBLK) {
        // ---- L: one warp per row; lane covers 8 consecutive floats ----
        const int wid = threadIdx.x >> 5, lane = threadIdx.x & 31;
        const int rowg = blockIdx.x * 8 + wid;               // 0..BB*NN-1
        const float4* src = (const float4*)(l + (size_t)rowg * CC);
        float4 v0 = src[lane * 2];
        float4 v1 = src[lane * 2 + 1];
        float s = fmaf(v0.x, v0.x, fmaf(v0.y, v0.y, fmaf(v0.z, v0.z, v0.w * v0.w)));
        s = fmaf(v1.x, v1.x, fmaf(v1.y, v1.y, fmaf(v1.z, v1.z, fmaf(v1.w, v1.w, s))));
#pragma unroll
        for (int o = 16; o; o >>= 1) s += __shfl_xor_sync(0xffffffffu, s, o);
        uint32_t p0, p1, p2, p3;
        asm("cvt.rn.bf16x2.f32 %0, %1, %2;" : "=r"(p0) : "f"(v0.y), "f"(v0.x));
        asm("cvt.rn.bf16x2.f32 %0, %1, %2;" : "=r"(p1) : "f"(v0.w), "f"(v0.z));
        asm("cvt.rn.bf16x2.f32 %0, %1, %2;" : "=r"(p2) : "f"(v1.y), "f"(v1.x));
        asm("cvt.rn.bf16x2.f32 %0, %1, %2;" : "=r"(p3) : "f"(v1.w), "f"(v1.z));
        uint4* dst = (uint4*)(d_Lbf + (size_t)rowg * LPAD);  // rows contiguous at stride LPAD
        dst[lane] = make_uint4(p0, p1, p2, p3);
        if (lane == 0) d_rln[rowg] = LOG2E / (TAU_F * sqrtf(s));
    } else {
        // ---- G: block per (b, chunk); 8 warps split the c range ----
        const int bc = blockIdx.x - NLBLK;                   // 0..127
        const int b = bc >> 5, chunk = bc & 31;
        const int mp = threadIdx.x & 31;                     // m-pair 0..31
        const int cg = threadIdx.x >> 5;                     // warp = c-group
        const int m0 = chunk * TMC + mp * 2;
        const float* gp = g + (size_t)b * CC * MM + m0;
        char* dstb = (char*)(d_Gbf + (size_t)(b * NCH + chunk) * CC * TMC);
        float s0 = 0.f, s1 = 0.f;
#pragma unroll 8
        for (int ci = 0; ci < 32; ci++) {
            int c = cg * 32 + ci;
            float2 v = *(const float2*)(gp + (size_t)c * MM);
            s0 = fmaf(v.x, v.x, s0);
            s1 = fmaf(v.y, v.y, s1);
            uint32_t off = (uint32_t)(c * 128 + mp * 4);
            off ^= (uint32_t)((c & 7) << 4);                 // swizzle bits 4-6 by c&7
            *(__nv_bfloat162*)(dstb + off) = __floats2bfloat162_rn(v.x, v.y);
        }
        part[cg][mp] = make_float2(s0, s1);
        __syncthreads();
        if (threadIdx.x < 32) {
            float a0 = 0.f, a1 = 0.f;
#pragma unroll
            for (int w = 0; w < 8; w++) { a0 += part[w][threadIdx.x].x; a1 += part[w][threadIdx.x].y; }
            const int mg = b * MM + chunk * TMC + threadIdx.x * 2;
            d_rgn[mg]     = rsqrtf(a0);
            d_rgn[mg + 1] = rsqrtf(a1);
        }
    }
}

// ---------------------------------------------------------------------------
// Fused: GEMM1 (S = L.G) -> exp -> GEMM2 (O += W.G^T) -> out = l + O/rowsum
// ---------------------------------------------------------------------------
__global__ __launch_bounds__(256, 1)
void fused_mma_kernel(const float* __restrict__ l, float* __restrict__ out) {
    extern __shared__ char smraw[];
    char* gb = (char*)(((uintptr_t)smraw + 1023) & ~(uintptr_t)1023);
    const uint32_t base = smem_u32(gb);
    const int t = threadIdx.x, lane = t & 31, wid = t >> 5;
    const int q = lane & 3, lr = lane & 7, lg = lane >> 3;
    const int b = blockIdx.y, tile = blockIdx.x;

    // Stage L tile (flat copy; tile is exactly LS_U4 uint4)
    {
        const uint4* s4 = (const uint4*)(d_Lbf + (size_t)(b * NTILES + tile) * TILE_N * LPAD);
        uint4* d4 = (uint4*)(gb + SM_LS);
        for (int i = t; i < LS_U4; i += 256) d4[i] = s4[i];
    }
    // Stage G chunk 0 + gn chunk 0 via cp.async
    {
        const char* sg = (const char*)(d_Gbf + (size_t)(b * NCH) * CC * TMC);
#pragma unroll
        for (int i = 0; i < 8; i++)
            cpasync16(base + SM_GS + (uint32_t)((t + 256 * i) * 16), sg + (size_t)(t + 256 * i) * 16);
        if (t < 16)
            cpasync16(base + SM_GN + (uint32_t)(t * 16), (const char*)(d_rgn + b * MM) + t * 16);
        asm volatile("cp.async.commit_group;" ::: "memory");
    }

    const int row0 = tile * TILE_N + wid * 16 + (lane >> 2);  // lower row of this thread
    const float rln_lo = d_rln[b * NN + row0];
    const float rln_hi = d_rln[b * NN + row0 + 8];

    // ldmatrix addresses (16B-granular)
    const uint32_t aA0 = base + SM_LS
        + (uint32_t)((wid * 16 + (lg & 1) * 8 + lr) * (LPAD * 2)) + (uint32_t)((lg >> 1) * 16);
    uint32_t b1off[4];   // GEMM1 B (trans): c = kt*16 + (lg&1)*8 + lr; pair pp covers ntiles 2pp,2pp+1
#pragma unroll
    for (int pp = 0; pp < 4; pp++)
        b1off[pp] = (uint32_t)(((lg & 1) * 8 + lr) * 128)
                  + ((uint32_t)(pp * 32 + (lg >> 1) * 16) ^ (uint32_t)(lr << 4));
    const uint32_t b2off0 = (uint32_t)(lr * 128) + ((uint32_t)(lg * 16) ^ (uint32_t)(lr << 4));
    const uint32_t b2off1 = (uint32_t)(lr * 128) + ((uint32_t)(64 + lg * 16) ^ (uint32_t)(lr << 4));

    float O[32][4];
#pragma unroll
    for (int nt = 0; nt < 32; nt++) { O[nt][0] = O[nt][1] = O[nt][2] = O[nt][3] = 0.f; }
    float rs_lo = 0.f, rs_hi = 0.f;

    asm volatile("cp.async.wait_group 0;" ::: "memory");
    __syncthreads();

    for (int k = 0; k < NCH; k++) {
        const int s = k & 1;
        const uint32_t Gsb = base + SM_GS + (uint32_t)(s * GS_BYTES);

        // Async prefetch next chunk into the other slot (consumed in iter k+1)
        if (k + 1 < NCH) {
            const char* sg = (const char*)(d_Gbf + (size_t)(b * NCH + k + 1) * CC * TMC);
            const uint32_t dg = base + SM_GS + (uint32_t)((s ^ 1) * GS_BYTES);
#pragma unroll
            for (int i = 0; i < 8; i++)
                cpasync16(dg + (uint32_t)((t + 256 * i) * 16), sg + (size_t)(t + 256 * i) * 16);
            if (t < 16)
                cpasync16(base + SM_GN + (uint32_t)((s ^ 1) * 256 + t * 16),
                          (const char*)(d_rgn + b * MM + (k + 1) * TMC) + t * 16);
            asm volatile("cp.async.commit_group;" ::: "memory");
        }

        // ---- GEMM1: S[16 rows][64 cols] per warp ----
        float S[8][4];
#pragma unroll
        for (int p = 0; p < 8; p++) S[p][0] = S[p][1] = S[p][2] = S[p][3] = 0.f;
#pragma unroll
        for (int kt = 0; kt < 16; kt++) {
            uint32_t A[4];
            ldsm_x4(aA0 + (uint32_t)(kt * 32), A);
            const uint32_t crow = Gsb + (uint32_t)(kt * 2048);
#pragma unroll
            for (int pp = 0; pp < 4; pp++) {
                uint32_t B4[4];
                ldsm_x4t(crow + b1off[pp], B4);
                mma16816(S[2 * pp],     A, B4[0], B4[1]);
                mma16816(S[2 * pp + 1], A, B4[2], B4[3]);
            }
        }

        // ---- exp -> W fragments (registers only) + rowsum ----
        const float* gnp = (const float*)(gb + SM_GN + s * 256);
        uint32_t afr[4][4];
#pragma unroll
        for (int p = 0; p < 8; p++) {
            float2 gn2 = *(const float2*)(gnp + p * 8 + q * 2);
            float w0 = ex2f(S[p][0] * rln_lo * gn2.x);
            float w1 = ex2f(S[p][1] * rln_lo * gn2.y);
            float w2 = ex2f(S[p][2] * rln_hi * gn2.x);
            float w3 = ex2f(S[p][3] * rln_hi * gn2.y);
            rs_lo += w0 + w1;
            rs_hi += w2 + w3;
            uint32_t pk01, pk23;
            asm("cvt.rn.bf16x2.f32 %0, %1, %2;" : "=r"(pk01) : "f"(w1), "f"(w0));
            asm("cvt.rn.bf16x2.f32 %0, %1, %2;" : "=r"(pk23) : "f"(w3), "f"(w2));
            afr[p >> 1][(p & 1) * 2 + 0] = pk01;
            afr[p >> 1][(p & 1) * 2 + 1] = pk23;
        }

        // ---- GEMM2: O[16 rows][256 cols] += W[16][64] . G^T[64][256] ----
#pragma unroll
        for (int nt = 0; nt < 32; nt++) {
            const uint32_t nb = Gsb + (uint32_t)(nt * 1024);
            uint32_t B0[4], B1[4];
            ldsm_x4(nb + b2off0, B0);
            ldsm_x4(nb + b2off1, B1);
            mma16816(O[nt], afr[0], B0[0], B0[1]);
            mma16816(O[nt], afr[1], B0[2], B0[3]);
            mma16816(O[nt], afr[2], B1[0], B1[1]);
            mma16816(O[nt], afr[3], B1[2], B1[3]);
        }
        if (k + 1 < NCH) asm volatile("cp.async.wait_group 0;" ::: "memory");
        __syncthreads();
    }

    // ---- rowsum reduce across the lane quad (cols partition over q) ----
    rs_lo += __shfl_xor_sync(0xffffffffu, rs_lo, 1);
    rs_lo += __shfl_xor_sync(0xffffffffu, rs_lo, 2);
    rs_hi += __shfl_xor_sync(0xffffffffu, rs_hi, 1);
    rs_hi += __shfl_xor_sync(0xffffffffu, rs_hi, 2);
    const float ri_lo = 1.0f / rs_lo;
    const float ri_hi = 1.0f / rs_hi;

    // ---- Epilogue: out = l + O / rowsum ----
    const float* lrow_lo = l + ((size_t)b * NN + row0) * CC;
    const float* lrow_hi = lrow_lo + 8 * CC;
    float* orow_lo = out + ((size_t)b * NN + row0) * CC;
    float* orow_hi = orow_lo + 8 * CC;
#pragma unroll
    for (int nt = 0; nt < 32; nt++) {
        const int c = nt * 8 + q * 2;
        float2 lv0 = *(const float2*)(lrow_lo + c);
        float2 ov0;
        ov0.x = fmaf(O[nt][0], ri_lo, lv0.x);
        ov0.y = fmaf(O[nt][1], ri_lo, lv0.y);
        *(float2*)(orow_lo + c) = ov0;
        float2 lv1 = *(const float2*)(lrow_hi + c);
        float2 ov1;
        ov1.x = fmaf(O[nt][2], ri_hi, lv1.x);
        ov1.y = fmaf(O[nt][3], ri_hi, lv1.y);
        *(float2*)(orow_hi + c) = ov1;
    }
}

// ---------------------------------------------------------------------------
extern "C" void kernel_launch(void* const* d_in, const int* in_sizes, int n_in,
                              void* d_out, int out_size) {
    (void)in_sizes; (void)n_in; (void)out_size;
    const float* l = (const float*)d_in[0];   // [B, N, C]
    const float* g = (const float*)d_in[1];   // [B, C, M]
    float* out = (float*)d_out;               // [B, N, C]

    cudaFuncSetAttribute(fused_mma_kernel,
                         cudaFuncAttributeMaxDynamicSharedMemorySize, SMEM_ALLOC);

    prep_kernel<<<NLBLK + BB * NCH, 256>>>(l, g);
    fused_mma_kernel<<<dim3(NTILES, BB), 256, SMEM_ALLOC>>>(l, out);
}

// round 15
// speedup vs baseline: 9.7613x; 1.0205x over previous
#include <cuda_runtime.h>
#include <cuda_bf16.h>
#include <stdint.h>

#define BB 4
#define NN 4096
#define CC 256
#define MM 2048
#define TAU_F 0.4f
#define LOG2E 1.4426950408889634f

#define TMC 64
#define NCH (MM / TMC)          // 32 chunks
#define TILE_N 64
#define NTILES (NN / TILE_N)    // 64 tiles
#define NTHR 128                // 4 warps
#define LPAD 264                // halves per L row (528 B = 33*16B -> conflict-free LDSM)

#define SM_LS 0
#define LS_BYTES (TILE_N * LPAD * 2)      // 33792 (1024-aligned: 33*1024)
#define LS_U4 (LS_BYTES / 16)             // 2112
#define SM_GS LS_BYTES
#define GS_BYTES (CC * TMC * 2)           // 32768
#define SM_GN (SM_GS + 2 * GS_BYTES)      // 99328
#define SMEM_ALLOC (SM_GN + 512 + 1024)   // 100864 -> 2 CTAs/SM

#define NLBLK (BB * NN / 8)               // 2048 L-blocks (8 rows each)

__device__ __align__(16) __nv_bfloat16 d_Lbf[BB * NN * LPAD];
__device__ __align__(16) __nv_bfloat16 d_Gbf[BB * NCH * CC * TMC];
__device__ float d_rln[BB * NN];   // log2e / (tau * ||l_n||)
__device__ float d_rgn[BB * MM];   // 1 / ||g_m||

// ---------------------------------------------------------------------------
__device__ __forceinline__ uint32_t smem_u32(const void* p) {
    uint32_t a;
    asm("{ .reg .u64 t; cvta.to.shared.u64 t, %1; cvt.u32.u64 %0, t; }" : "=r"(a) : "l"(p));
    return a;
}
__device__ __forceinline__ void ldsm_x4(uint32_t a, uint32_t* r) {
    asm volatile("ldmatrix.sync.aligned.m8n8.x4.shared.b16 {%0,%1,%2,%3}, [%4];"
                 : "=r"(r[0]), "=r"(r[1]), "=r"(r[2]), "=r"(r[3]) : "r"(a));
}
__device__ __forceinline__ void ldsm_x4t(uint32_t a, uint32_t* r) {
    asm volatile("ldmatrix.sync.aligned.m8n8.x4.trans.shared.b16 {%0,%1,%2,%3}, [%4];"
                 : "=r"(r[0]), "=r"(r[1]), "=r"(r[2]), "=r"(r[3]) : "r"(a));
}
__device__ __forceinline__ void mma16816(float* d, const uint32_t* a, uint32_t b0, uint32_t b1) {
    asm volatile("mma.sync.aligned.m16n8k16.row.col.f32.bf16.bf16.f32 "
                 "{%0,%1,%2,%3}, {%4,%5,%6,%7}, {%8,%9}, {%0,%1,%2,%3};"
                 : "+f"(d[0]), "+f"(d[1]), "+f"(d[2]), "+f"(d[3])
                 : "r"(a[0]), "r"(a[1]), "r"(a[2]), "r"(a[3]), "r"(b0), "r"(b1));
}
__device__ __forceinline__ float ex2f(float x) {
    float r; asm("ex2.approx.ftz.f32 %0, %1;" : "=f"(r) : "f"(x)); return r;
}
__device__ __forceinline__ void cpasync16(uint32_t dst, const void* src) {
    asm volatile("cp.async.cg.shared.global [%0], [%1], 16;" :: "r"(dst), "l"(src) : "memory");
}

// ---------------------------------------------------------------------------
// Merged prep: blocks [0,NLBLK) do L (warp per row); blocks [NLBLK, +128) do G
// ---------------------------------------------------------------------------
__global__ __launch_bounds__(256) void prep_kernel(const float* __restrict__ l,
                                                   const float* __restrict__ g) {
    __shared__ float2 part[8][32];
    if (blockIdx.x < NLBLK) {
        // ---- L: one warp per row; lane covers 8 consecutive floats ----
        const int wid = threadIdx.x >> 5, lane = threadIdx.x & 31;
        const int rowg = blockIdx.x * 8 + wid;               // 0..BB*NN-1
        const float4* src = (const float4*)(l + (size_t)rowg * CC);
        float4 v0 = src[lane * 2];
        float4 v1 = src[lane * 2 + 1];
        float s = fmaf(v0.x, v0.x, fmaf(v0.y, v0.y, fmaf(v0.z, v0.z, v0.w * v0.w)));
        s = fmaf(v1.x, v1.x, fmaf(v1.y, v1.y, fmaf(v1.z, v1.z, fmaf(v1.w, v1.w, s))));
#pragma unroll
        for (int o = 16; o; o >>= 1) s += __shfl_xor_sync(0xffffffffu, s, o);
        uint32_t p0, p1, p2, p3;
        asm("cvt.rn.bf16x2.f32 %0, %1, %2;" : "=r"(p0) : "f"(v0.y), "f"(v0.x));
        asm("cvt.rn.bf16x2.f32 %0, %1, %2;" : "=r"(p1) : "f"(v0.w), "f"(v0.z));
        asm("cvt.rn.bf16x2.f32 %0, %1, %2;" : "=r"(p2) : "f"(v1.y), "f"(v1.x));
        asm("cvt.rn.bf16x2.f32 %0, %1, %2;" : "=r"(p3) : "f"(v1.w), "f"(v1.z));
        uint4* dst = (uint4*)(d_Lbf + (size_t)rowg * LPAD);
        dst[lane] = make_uint4(p0, p1, p2, p3);
        if (lane == 0) d_rln[rowg] = LOG2E / (TAU_F * sqrtf(s));
    } else {
        // ---- G: block per (b, chunk); 8 warps split the c range ----
        const int bc = blockIdx.x - NLBLK;                   // 0..127
        const int b = bc >> 5, chunk = bc & 31;
        const int mp = threadIdx.x & 31;                     // m-pair 0..31
        const int cg = threadIdx.x >> 5;                     // warp = c-group
        const int m0 = chunk * TMC + mp * 2;
        const float* gp = g + (size_t)b * CC * MM + m0;
        char* dstb = (char*)(d_Gbf + (size_t)(b * NCH + chunk) * CC * TMC);
        float s0 = 0.f, s1 = 0.f;
#pragma unroll 8
        for (int ci = 0; ci < 32; ci++) {
            int c = cg * 32 + ci;
            float2 v = *(const float2*)(gp + (size_t)c * MM);
            s0 = fmaf(v.x, v.x, s0);
            s1 = fmaf(v.y, v.y, s1);
            uint32_t off = (uint32_t)(c * 128 + mp * 4);
            off ^= (uint32_t)((c & 7) << 4);                 // swizzle bits 4-6 by c&7
            *(__nv_bfloat162*)(dstb + off) = __floats2bfloat162_rn(v.x, v.y);
        }
        part[cg][mp] = make_float2(s0, s1);
        __syncthreads();
        if (threadIdx.x < 32) {
            float a0 = 0.f, a1 = 0.f;
#pragma unroll
            for (int w = 0; w < 8; w++) { a0 += part[w][threadIdx.x].x; a1 += part[w][threadIdx.x].y; }
            const int mg = b * MM + chunk * TMC + threadIdx.x * 2;
            d_rgn[mg]     = rsqrtf(a0);
            d_rgn[mg + 1] = rsqrtf(a1);
        }
    }
}

// ---------------------------------------------------------------------------
// Fused: GEMM1 (S = L.G) -> exp -> GEMM2 (O += W.G^T) -> out = l + O/rowsum
// 4 warps x 16 rows = 64-row tile; 2 CTAs resident per SM (explicit).
// ---------------------------------------------------------------------------
__global__ __launch_bounds__(NTHR, 2)
void fused_mma_kernel(const float* __restrict__ l, float* __restrict__ out) {
    extern __shared__ char smraw[];
    char* gb = (char*)(((uintptr_t)smraw + 1023) & ~(uintptr_t)1023);
    const uint32_t base = smem_u32(gb);
    const int t = threadIdx.x, lane = t & 31, wid = t >> 5;
    const int q = lane & 3, lr = lane & 7, lg = lane >> 3;
    const int b = blockIdx.y, tile = blockIdx.x;

    // Stage L tile (flat copy; rows contiguous at stride LPAD)
    {
        const uint4* s4 = (const uint4*)(d_Lbf + (size_t)(b * NN + tile * TILE_N) * LPAD);
        uint4* d4 = (uint4*)(gb + SM_LS);
        for (int i = t; i < LS_U4; i += NTHR) d4[i] = s4[i];
    }
    // Stage G chunk 0 + gn chunk 0 via cp.async
    {
        const char* sg = (const char*)(d_Gbf + (size_t)(b * NCH) * CC * TMC);
#pragma unroll
        for (int i = 0; i < 16; i++)
            cpasync16(base + SM_GS + (uint32_t)((t + NTHR * i) * 16), sg + (size_t)(t + NTHR * i) * 16);
        if (t < 16)
            cpasync16(base + SM_GN + (uint32_t)(t * 16), (const char*)(d_rgn + b * MM) + t * 16);
        asm volatile("cp.async.commit_group;" ::: "memory");
    }

    const int row0 = tile * TILE_N + wid * 16 + (lane >> 2);  // lower row of this thread
    const float rln_lo = d_rln[b * NN + row0];
    const float rln_hi = d_rln[b * NN + row0 + 8];

    // ldmatrix addresses (16B-granular)
    const uint32_t aA0 = base + SM_LS
        + (uint32_t)((wid * 16 + (lg & 1) * 8 + lr) * (LPAD * 2)) + (uint32_t)((lg >> 1) * 16);
    uint32_t b1off[4];   // GEMM1 B (trans): c = kt*16 + (lg&1)*8 + lr; pair pp covers ntiles 2pp,2pp+1
#pragma unroll
    for (int pp = 0; pp < 4; pp++)
        b1off[pp] = (uint32_t)(((lg & 1) * 8 + lr) * 128)
                  + ((uint32_t)(pp * 32 + (lg >> 1) * 16) ^ (uint32_t)(lr << 4));
    const uint32_t b2off0 = (uint32_t)(lr * 128) + ((uint32_t)(lg * 16) ^ (uint32_t)(lr << 4));
    const uint32_t b2off1 = (uint32_t)(lr * 128) + ((uint32_t)(64 + lg * 16) ^ (uint32_t)(lr << 4));

    float O[32][4];
#pragma unroll
    for (int nt = 0; nt < 32; nt++) { O[nt][0] = O[nt][1] = O[nt][2] = O[nt][3] = 0.f; }
    float rs_lo = 0.f, rs_hi = 0.f;

    asm volatile("cp.async.wait_group 0;" ::: "memory");
    __syncthreads();

    for (int k = 0; k < NCH; k++) {
        const int s = k & 1;
        const uint32_t Gsb = base + SM_GS + (uint32_t)(s * GS_BYTES);

        // Async prefetch next chunk into the other slot (consumed in iter k+1)
        if (k + 1 < NCH) {
            const char* sg = (const char*)(d_Gbf + (size_t)(b * NCH + k + 1) * CC * TMC);
            const uint32_t dg = base + SM_GS + (uint32_t)((s ^ 1) * GS_BYTES);
#pragma unroll
            for (int i = 0; i < 16; i++)
                cpasync16(dg + (uint32_t)((t + NTHR * i) * 16), sg + (size_t)(t + NTHR * i) * 16);
            if (t < 16)
                cpasync16(base + SM_GN + (uint32_t)((s ^ 1) * 256 + t * 16),
                          (const char*)(d_rgn + b * MM + (k + 1) * TMC) + t * 16);
            asm volatile("cp.async.commit_group;" ::: "memory");
        }

        // ---- GEMM1: S[16 rows][64 cols] per warp ----
        float S[8][4];
#pragma unroll
        for (int p = 0; p < 8; p++) S[p][0] = S[p][1] = S[p][2] = S[p][3] = 0.f;
#pragma unroll
        for (int kt = 0; kt < 16; kt++) {
            uint32_t A[4];
            ldsm_x4(aA0 + (uint32_t)(kt * 32), A);
            const uint32_t crow = Gsb + (uint32_t)(kt * 2048);
#pragma unroll
            for (int pp = 0; pp < 4; pp++) {
                uint32_t B4[4];
                ldsm_x4t(crow + b1off[pp], B4);
                mma16816(S[2 * pp],     A, B4[0], B4[1]);
                mma16816(S[2 * pp + 1], A, B4[2], B4[3]);
            }
        }

        // ---- exp -> W fragments (registers only) + rowsum ----
        const float* gnp = (const float*)(gb + SM_GN + s * 256);
        uint32_t afr[4][4];
#pragma unroll
        for (int p = 0; p < 8; p++) {
            float2 gn2 = *(const float2*)(gnp + p * 8 + q * 2);
            float w0 = ex2f(S[p][0] * rln_lo * gn2.x);
            float w1 = ex2f(S[p][1] * rln_lo * gn2.y);
            float w2 = ex2f(S[p][2] * rln_hi * gn2.x);
            float w3 = ex2f(S[p][3] * rln_hi * gn2.y);
            rs_lo += w0 + w1;
            rs_hi += w2 + w3;
            uint32_t pk01, pk23;
            asm("cvt.rn.bf16x2.f32 %0, %1, %2;" : "=r"(pk01) : "f"(w1), "f"(w0));
            asm("cvt.rn.bf16x2.f32 %0, %1, %2;" : "=r"(pk23) : "f"(w3), "f"(w2));
            afr[p >> 1][(p & 1) * 2 + 0] = pk01;
            afr[p >> 1][(p & 1) * 2 + 1] = pk23;
        }

        // ---- GEMM2: O[16 rows][256 cols] += W[16][64] . G^T[64][256] ----
#pragma unroll
        for (int nt = 0; nt < 32; nt++) {
            const uint32_t nb = Gsb + (uint32_t)(nt * 1024);
            uint32_t B0[4], B1[4];
            ldsm_x4(nb + b2off0, B0);
            ldsm_x4(nb + b2off1, B1);
            mma16816(O[nt], afr[0], B0[0], B0[1]);
            mma16816(O[nt], afr[1], B0[2], B0[3]);
            mma16816(O[nt], afr[2], B1[0], B1[1]);
            mma16816(O[nt], afr[3], B1[2], B1[3]);
        }
        if (k + 1 < NCH) asm volatile("cp.async.wait_group 0;" ::: "memory");
        __syncthreads();
    }

    // ---- rowsum reduce across the lane quad (cols partition over q) ----
    rs_lo += __shfl_xor_sync(0xffffffffu, rs_lo, 1);
    rs_lo += __shfl_xor_sync(0xffffffffu, rs_lo, 2);
    rs_hi += __shfl_xor_sync(0xffffffffu, rs_hi, 1);
    rs_hi += __shfl_xor_sync(0xffffffffu, rs_hi, 2);
    const float ri_lo = 1.0f / rs_lo;
    const float ri_hi = 1.0f / rs_hi;

    // ---- Epilogue: out = l + O / rowsum ----
    const float* lrow_lo = l + ((size_t)b * NN + row0) * CC;
    const float* lrow_hi = lrow_lo + 8 * CC;
    float* orow_lo = out + ((size_t)b * NN + row0) * CC;
    float* orow_hi = orow_lo + 8 * CC;
#pragma unroll
    for (int nt = 0; nt < 32; nt++) {
        const int c = nt * 8 + q * 2;
        float2 lv0 = *(const float2*)(lrow_lo + c);
        float2 ov0;
        ov0.x = fmaf(O[nt][0], ri_lo, lv0.x);
        ov0.y = fmaf(O[nt][1], ri_lo, lv0.y);
        *(float2*)(orow_lo + c) = ov0;
        float2 lv1 = *(const float2*)(lrow_hi + c);
        float2 ov1;
        ov1.x = fmaf(O[nt][2], ri_hi, lv1.x);
        ov1.y = fmaf(O[nt][3], ri_hi, lv1.y);
        *(float2*)(orow_hi + c) = ov1;
    }
}

// ---------------------------------------------------------------------------
extern "C" void kernel_launch(void* const* d_in, const int* in_sizes, int n_in,
                              void* d_out, int out_size) {
    (void)in_sizes; (void)n_in; (void)out_size;
    const float* l = (const float*)d_in[0];   // [B, N, C]
    const float* g = (const float*)d_in[1];   // [B, C, M]
    float* out = (float*)d_out;               // [B, N, C]

    cudaFuncSetAttribute(fused_mma_kernel,
                         cudaFuncAttributeMaxDynamicSharedMemorySize, SMEM_ALLOC);

    prep_kernel<<<NLBLK + BB * NCH, 256>>>(l, g);
    fused_mma_kernel<<<dim3(NTILES, BB), NTHR, SMEM_ALLOC>>>(l, out);
}